// round 2
// baseline (speedup 1.0000x reference)
#include <cuda_runtime.h>

// Problem constants (fixed by the benchmark shapes)
#define B_   8
#define CI_  64
#define T_   16
#define H_   64
#define W_   64
#define CO_  64

#define CIC  8     // c_in chunk held in smem
#define COT  16    // c_out tile per CTA
#define RT   8     // output rows per CTA

// Direct 3x3 conv, pad=1. alpha is folded into the weights per (b,t):
//   out = sum_i (alpha_i * W[o,i]) (*) x[i]
__global__ __launch_bounds__(256, 3)
void tada_conv_kernel(const float* __restrict__ x,
                      const float* __restrict__ alpha,
                      const float* __restrict__ weight,
                      const float* __restrict__ bias,
                      float* __restrict__ out)
{
    __shared__ float xs[CIC][RT + 2][W_ + 2];   // 8*10*66*4 = 21120 B
    __shared__ float ws[CIC][9][COT];           // 8*9*16*4  =  4608 B

    const int bt  = blockIdx.x;        // 0..127
    const int b   = bt >> 4;
    const int t   = bt & 15;
    const int y0  = blockIdx.y * RT;   // 0,8,...,56
    const int co0 = blockIdx.z * COT;  // 0,16,32,48

    const int tid = threadIdx.x;       // 0..255
    const int tx  = tid & 63;          // output column
    const int tg  = tid >> 6;          // 0..3 -> 4 c_out each

    float acc[RT][4];
#pragma unroll
    for (int y = 0; y < RT; y++)
#pragma unroll
        for (int j = 0; j < 4; j++) acc[y][j] = 0.f;

    for (int cc = 0; cc < CI_; cc += CIC) {
        __syncthreads();  // protect smem from previous chunk's readers

        // Load weight chunk, scaled by alpha[b, ci, t] (folds the calibration)
        for (int i = tid; i < CIC * 9 * COT; i += 256) {
            int ci  = i / (9 * COT);
            int rem = i - ci * (9 * COT);
            int k   = rem / COT;
            int co  = rem - k * COT;
            float a = alpha[(b * CI_ + cc + ci) * T_ + t];
            ws[ci][k][co] = weight[((co0 + co) * CI_ + cc + ci) * 9 + k] * a;
        }

        // Load x tile (halo of 1 on all sides, zero-padded)
        for (int i = tid; i < CIC * (RT + 2) * (W_ + 2); i += 256) {
            int ci  = i / ((RT + 2) * (W_ + 2));
            int rem = i - ci * ((RT + 2) * (W_ + 2));
            int r   = rem / (W_ + 2);
            int c   = rem - r * (W_ + 2);
            int gy  = y0 + r - 1;
            int gx  = c - 1;
            float v = 0.f;
            if ((unsigned)gy < (unsigned)H_ && (unsigned)gx < (unsigned)W_)
                v = x[(((b * CI_ + cc + ci) * T_ + t) * H_ + gy) * W_ + gx];
            xs[ci][r][c] = v;
        }
        __syncthreads();

        // Compute: per (ci,kh): 12 broadcast weight LDS + 24 x LDS + 96 FFMA
        for (int ci = 0; ci < CIC; ci++) {
#pragma unroll
            for (int kh = 0; kh < 3; kh++) {
                float w0[4], w1[4], w2[4];
#pragma unroll
                for (int j = 0; j < 4; j++) {
                    w0[j] = ws[ci][kh * 3 + 0][tg * 4 + j];
                    w1[j] = ws[ci][kh * 3 + 1][tg * 4 + j];
                    w2[j] = ws[ci][kh * 3 + 2][tg * 4 + j];
                }
#pragma unroll
                for (int y = 0; y < RT; y++) {
                    float x0 = xs[ci][y + kh][tx + 0];
                    float x1 = xs[ci][y + kh][tx + 1];
                    float x2 = xs[ci][y + kh][tx + 2];
#pragma unroll
                    for (int j = 0; j < 4; j++)
                        acc[y][j] += w0[j] * x0 + w1[j] * x1 + w2[j] * x2;
                }
            }
        }
    }

    // Epilogue: bias + coalesced stores
    float bv[4];
#pragma unroll
    for (int j = 0; j < 4; j++) bv[j] = __ldg(&bias[co0 + tg * 4 + j]);

#pragma unroll
    for (int j = 0; j < 4; j++) {
        const int co = co0 + tg * 4 + j;
        float* op = out + (((b * CO_ + co) * T_ + t) * H_ + y0) * W_ + tx;
#pragma unroll
        for (int y = 0; y < RT; y++)
            op[y * W_] = acc[y][j] + bv[j];
    }
}

extern "C" void kernel_launch(void* const* d_in, const int* in_sizes, int n_in,
                              void* d_out, int out_size)
{
    const float* x      = (const float*)d_in[0];
    const float* alpha  = (const float*)d_in[1];
    const float* weight = (const float*)d_in[2];
    const float* bias   = (const float*)d_in[3];
    float* out          = (float*)d_out;

    dim3 grid(B_ * T_, H_ / RT, CO_ / COT);  // (128, 8, 4) = 4096 CTAs
    tada_conv_kernel<<<grid, 256>>>(x, alpha, weight, bias, out);
}